// round 13
// baseline (speedup 1.0000x reference)
#include <cuda_runtime.h>
#include <cstdint>

typedef unsigned long long ull;

#define TT    2048
#define BB    128
#define IN_D  256
#define HH    256
#define G3    768
#define NBLK  96
#define HPAD  260
#define CHUNK_PER_T (3 * G3 * BB)   /* 294912 floats per timestep */

// ---------------- static device scratch (no allocation APIs allowed) ----------
__device__ float g_GXa[(size_t)1024 * CHUNK_PER_T];   // t in [0,1024)
__device__ float g_GXb[(size_t)1024 * CHUNK_PER_T];   // t in [1024,2048)
__device__ float g_H[2][3][BB][HH];                   // double-buffered hidden state
__device__ unsigned g_bar;                            // grid barrier arrival counter
__device__ unsigned g_done;                           // exit counter (for reset)

__device__ __forceinline__ float* GXptr(int t) {
    return (t < 1024) ? (g_GXa + (size_t)t * CHUNK_PER_T)
                      : (g_GXb + (size_t)(t - 1024) * CHUNK_PER_T);
}

// ---------------- packed f32x2 helpers ----------------
__device__ __forceinline__ ull pk2(float v) {
    ull r;
    asm("mov.b64 %0, {%1, %2};" : "=l"(r) : "f"(v), "f"(v));
    return r;
}
__device__ __forceinline__ void fma2(ull& acc, ull a, ull b) {
    asm("fma.rn.f32x2 %0, %1, %2, %0;" : "+l"(acc) : "l"(a), "l"(b));
}
__device__ __forceinline__ float2 upk(ull v) {
    float2 f;
    asm("mov.b64 {%0, %1}, %2;" : "=f"(f.x), "=f"(f.y) : "l"(v));
    return f;
}

// ======================================================================
// Kernel 1: GX[t][k][o][b] = sum_i x[b][t][i] * Wx[k][i][o] + bx[k][o]
// grid (36, 2048): x = kk*12 + otile(64 outputs), y = t. 256 threads.
// Thread tile: 8 outputs (4 f32x2 pairs, og = tid>>5) x 4 batches
// (b = bg, bg+32, bg+64, bg+96; bg = tid&31).
// ======================================================================
__global__ __launch_bounds__(256, 2) void k_xgemm(const float* __restrict__ x,
                                                  const float* __restrict__ Wx,
                                                  const float* __restrict__ bx)
{
    __shared__ float Xs[128 * 33];   // [b][i] rows padded to 33 (conflict-free)
    __shared__ float Ws[32 * 64];    // [i][o]

    const int t   = blockIdx.y;
    const int kk  = blockIdx.x / 12;
    const int ob  = (blockIdx.x % 12) * 64;
    const int tid = threadIdx.x;
    const int bg  = tid & 31;
    const int og  = tid >> 5;

    ull acc[4][4];                   // [o-pair][batch-slot]
    #pragma unroll
    for (int p = 0; p < 4; ++p)
        #pragma unroll
        for (int j = 0; j < 4; ++j) acc[p][j] = 0ull;

    const ull* Wsu = (const ull*)Ws;

    for (int kc = 0; kc < 8; ++kc) {
        // X chunk: 128 b x 32 i, coalesced float4 global, scalar conflict-free STS
        #pragma unroll
        for (int p = 0; p < 4; ++p) {
            int idx = tid + p * 256;
            int b = idx >> 3, f = idx & 7;
            float4 v = *(const float4*)(x + ((size_t)b * TT + t) * IN_D + kc * 32 + f * 4);
            Xs[b * 33 + f * 4 + 0] = v.x;
            Xs[b * 33 + f * 4 + 1] = v.y;
            Xs[b * 33 + f * 4 + 2] = v.z;
            Xs[b * 33 + f * 4 + 3] = v.w;
        }
        // W chunk: 32 i x 64 o
        #pragma unroll
        for (int p = 0; p < 2; ++p) {
            int idx = tid + p * 256;
            int i = idx >> 4, f = idx & 15;
            *(float4*)(Ws + i * 64 + f * 4) =
                *(const float4*)(Wx + ((size_t)kk * IN_D + kc * 32 + i) * G3 + ob + f * 4);
        }
        __syncthreads();

        #pragma unroll 8
        for (int i = 0; i < 32; ++i) {
            ull w0 = Wsu[i * 32 + og * 4 + 0];   // warp-uniform -> LDS broadcast
            ull w1 = Wsu[i * 32 + og * 4 + 1];
            ull w2 = Wsu[i * 32 + og * 4 + 2];
            ull w3 = Wsu[i * 32 + og * 4 + 3];
            #pragma unroll
            for (int j = 0; j < 4; ++j) {
                ull a = pk2(Xs[(bg + 32 * j) * 33 + i]);
                fma2(acc[0][j], a, w0);
                fma2(acc[1][j], a, w1);
                fma2(acc[2][j], a, w2);
                fma2(acc[3][j], a, w3);
            }
        }
        __syncthreads();
    }

    float* GX = GXptr(t);
    #pragma unroll
    for (int p = 0; p < 4; ++p) {
        int o0 = ob + og * 8 + 2 * p;
        float c0 = __ldg(bx + kk * G3 + o0);
        float c1 = __ldg(bx + kk * G3 + o0 + 1);
        #pragma unroll
        for (int j = 0; j < 4; ++j) {
            float2 v = upk(acc[p][j]);
            int b = bg + 32 * j;                 // coalesced across lanes
            GX[((size_t)kk * G3 + o0    ) * BB + b] = v.x + c0;
            GX[((size_t)kk * G3 + o0 + 1) * BB + b] = v.y + c1;
        }
    }
}

// ======================================================================
// Grid barrier: 96 co-resident blocks, accumulating generation counter.
// Canonical pattern: per-thread fence -> block sync -> one arrival atomic
// -> spin (with backoff) -> fence -> block sync.
// ======================================================================
__device__ __forceinline__ void arrive_wait(unsigned target)
{
    __threadfence();          // publish this thread's h stores (L2)
    __syncthreads();
    if (threadIdx.x == 0) {
        atomicAdd(&g_bar, 1u);
        unsigned v;
        for (;;) {
            asm volatile("ld.volatile.global.u32 %0, [%1];"
                         : "=r"(v) : "l"(&g_bar) : "memory");
            if (v >= target) break;
            __nanosleep(40);  // backoff: keep 96 spinners off the L2 line
        }
        __threadfence();
    }
    __syncthreads();
}

// ======================================================================
// Kernel 2: persistent recurrence. 96 blocks x 128 threads (1 block/SM,
// forced by 131.6 KB dynamic smem -> all co-resident in wave 1).
// Block = (kk, 32-unit slice J0, 32-batch tile B0). Wh slice (96 KB)
// resident in shared for all 2048 steps; h double-buffered in global
// (L1-bypassed: L1 is not cross-SM coherent within a launch).
// Thread tile: 3 gates x 1 unit-pair (f32x2) x 4 batches.
// ======================================================================
__global__ __launch_bounds__(128, 1) void k_recur(const float* __restrict__ h0,
                                                  const float* __restrict__ Wh,
                                                  const float* __restrict__ bh)
{
    extern __shared__ float sm[];
    float* Whs = sm;                   // [3][256][32] : Whs[(g*256+i)*32 + u]
    float* Hs  = sm + 3 * 256 * 32;    // [32][HPAD]   : h tile (full 256 units)
    const ull* Whsu = (const ull*)Whs;

    const int tid = threadIdx.x;
    const int blk = blockIdx.x;
    const int kk  = blk / 32;
    const int rem = blk - kk * 32;
    const int J0  = (rem & 7) * 32;    // unit slice base
    const int B0  = (rem >> 3) * 32;   // batch tile base
    const int bg  = tid & 7;           // batches: bg, bg+8, bg+16, bg+24
    const int ug  = tid >> 3;          // 0..15, unit pair u0 = 2*ug
    const int u0  = 2 * ug;

    // Resident Wh slice: Whs[g][i][u] = Wh[kk][i][g*256 + J0 + u]  (coalesced)
    for (int idx = tid; idx < 3 * 256 * 32; idx += 128) {
        int u = idx & 31;
        int i = (idx >> 5) & 255;
        int g = idx >> 13;
        Whs[idx] = Wh[((size_t)kk * HH + i) * G3 + g * HH + J0 + u];
    }
    float2 bhv[3];
    #pragma unroll
    for (int g = 0; g < 3; ++g)
        bhv[g] = *(const float2*)(bh + kk * G3 + g * HH + J0 + u0);

    // Initial hidden state into buffer 0 (rewritten every launch: deterministic)
    for (int idx = tid; idx < 32 * 32; idx += 128) {
        int r = idx >> 5, u = idx & 31;
        __stcg(&g_H[0][kk][B0 + r][J0 + u],
               h0[((size_t)kk * BB + B0 + r) * HH + J0 + u]);
    }
    arrive_wait(NBLK * 1u);

    for (int s = 0; s < TT; ++s) {
        const int cur = s & 1, nxt = cur ^ 1;
        const float* GX = GXptr(s);

        // Prefetch gx (+bx) — independent of h, issue early for MLP
        float gxr[3][2][4];
        #pragma unroll
        for (int g = 0; g < 3; ++g)
            #pragma unroll
            for (int uu = 0; uu < 2; ++uu) {
                size_t col = (size_t)kk * G3 + g * HH + J0 + u0 + uu;
                #pragma unroll
                for (int j = 0; j < 4; ++j)
                    gxr[g][uu][j] = __ldg(GX + col * BB + B0 + bg + 8 * j);
            }

        // Load h tile [32 x 256] from the current buffer (L2, not L1)
        #pragma unroll
        for (int p = 0; p < 16; ++p) {
            int idx = tid + p * 128;
            int r = idx >> 6, c4 = idx & 63;
            float4 v = __ldcg((const float4*)(&g_H[cur][kk][B0 + r][c4 * 4]));
            *(float4*)(Hs + r * HPAD + c4 * 4) = v;
        }
        __syncthreads();

        // gh = h_tile @ Wh_slice  (f32x2 over the unit pair)
        ull acc[3][4];
        #pragma unroll
        for (int g = 0; g < 3; ++g)
            #pragma unroll
            for (int j = 0; j < 4; ++j) acc[g][j] = 0ull;

        #pragma unroll 8
        for (int i = 0; i < 256; ++i) {
            ull w0 = Whsu[(0 * 256 + i) * 16 + ug];
            ull w1 = Whsu[(1 * 256 + i) * 16 + ug];
            ull w2 = Whsu[(2 * 256 + i) * 16 + ug];
            #pragma unroll
            for (int j = 0; j < 4; ++j) {
                ull a = pk2(Hs[(bg + 8 * j) * HPAD + i]);
                fma2(acc[0][j], a, w0);
                fma2(acc[1][j], a, w1);
                fma2(acc[2][j], a, w2);
            }
        }

        // Gates + state update
        #pragma unroll
        for (int j = 0; j < 4; ++j) {
            int b = B0 + bg + 8 * j;
            float2 gr = upk(acc[0][j]);
            float2 gz = upk(acc[1][j]);
            float2 gn = upk(acc[2][j]);
            gr.x += bhv[0].x; gr.y += bhv[0].y;
            gz.x += bhv[1].x; gz.y += bhv[1].y;
            gn.x += bhv[2].x; gn.y += bhv[2].y;
            float hn[2];
            #pragma unroll
            for (int uu = 0; uu < 2; ++uu) {
                float rh = uu ? gr.y : gr.x;
                float zh = uu ? gz.y : gz.x;
                float nh = uu ? gn.y : gn.x;
                float r = 1.f / (1.f + __expf(-(gxr[0][uu][j] + rh)));
                float z = 1.f / (1.f + __expf(-(gxr[1][uu][j] + zh)));
                float n = tanhf(gxr[2][uu][j] + r * nh);
                float hold = Hs[(bg + 8 * j) * HPAD + J0 + u0 + uu];
                hn[uu] = (1.f - z) * n + z * hold;
            }
            __stcg((float2*)&g_H[nxt][kk][b][J0 + u0], make_float2(hn[0], hn[1]));
        }

        arrive_wait((unsigned)NBLK * (unsigned)(s + 2));
    }

    // Reset barrier counters so every graph replay starts clean.
    if (tid == 0) {
        unsigned old = atomicAdd(&g_done, 1u);
        if (old == NBLK - 1) {
            g_bar = 0u;
            g_done = 0u;
            __threadfence();
        }
    }
}

// ======================================================================
// Epilogue: out = elu(sum_k h @ W_fc + b_fc); feature = mean_b h
// Final h lives in buffer 0 (2048 steps, even count of flips).
// ======================================================================
__global__ void k_fc(const float* __restrict__ Wfc, const float* __restrict__ bfc,
                     float* __restrict__ out)
{
    __shared__ float pooled[256];
    const int b = blockIdx.x, o = threadIdx.x;
    pooled[o] = g_H[0][0][b][o] + g_H[0][1][b][o] + g_H[0][2][b][o];
    __syncthreads();
    float s = __ldg(bfc + o);
    #pragma unroll 8
    for (int j = 0; j < 256; ++j)
        s = fmaf(pooled[j], __ldg(Wfc + j * 256 + o), s);
    out[b * 256 + o] = (s > 0.f) ? s : expm1f(s);
}

__global__ void k_feat(float* __restrict__ outF)
{
    const int k = blockIdx.x, u = threadIdx.x;
    float s = 0.f;
    #pragma unroll 4
    for (int b = 0; b < 128; ++b) s += g_H[0][k][b][u];
    outF[k * 256 + u] = s * (1.f / 128.f);
}

// ======================================================================
extern "C" void kernel_launch(void* const* d_in, const int* in_sizes, int n_in,
                              void* d_out, int out_size)
{
    const float* x   = (const float*)d_in[0];   // [128, 2048, 256]
    const float* h0  = (const float*)d_in[1];   // [1, 3, 128, 256]
    const float* Wx  = (const float*)d_in[2];   // [3, 256, 768]
    const float* Wh  = (const float*)d_in[3];   // [3, 256, 768]
    const float* bx  = (const float*)d_in[4];   // [3, 768]
    const float* bh  = (const float*)d_in[5];   // [3, 768]
    const float* Wfc = (const float*)d_in[6];   // [256, 256]
    const float* bfc = (const float*)d_in[7];   // [256]
    float* out = (float*)d_out;                 // out[128*256] ++ feature[3*256]

    const int smem_recur = (3 * 256 * 32 + 32 * HPAD) * (int)sizeof(float); // 131584
    cudaFuncSetAttribute(k_recur, cudaFuncAttributeMaxDynamicSharedMemorySize,
                         smem_recur);

    k_xgemm<<<dim3(36, 2048), 256>>>(x, Wx, bx);
    k_recur<<<NBLK, 128, smem_recur>>>(h0, Wh, bh);
    k_fc<<<128, 256>>>(Wfc, bfc, out);
    k_feat<<<3, 256>>>(out + 128 * 256);
    (void)in_sizes; (void)n_in; (void)out_size;
}

// round 15
// speedup vs baseline: 1.7171x; 1.7171x over previous
#include <cuda_runtime.h>
#include <cuda_bf16.h>
#include <cstdint>

typedef unsigned int uint32;

#define TT    2048
#define BB    128
#define IN_D  256
#define HH    256
#define G3    768
#define NBLK  96
#define CHUNK_PER_T (3 * G3 * BB)      /* floats per timestep of GX */

// ---------------- static device scratch ----------------
__device__ float g_GXa[(size_t)1024 * CHUNK_PER_T];      // t in [0,1024)
__device__ float g_GXb[(size_t)1024 * CHUNK_PER_T];      // t in [1024,2048)
__device__ unsigned short g_Xhi[(size_t)TT * BB * IN_D]; // x split  [t][b][i]
__device__ unsigned short g_Xlo[(size_t)TT * BB * IN_D];
__device__ unsigned short g_WxBhi[3 * G3 * IN_D];        // Wx^T split [n][k]
__device__ unsigned short g_WxBlo[3 * G3 * IN_D];
__device__ unsigned short g_Hh[2][3][BB][HH];            // h bf16 hi, dbl-buffered
__device__ unsigned short g_Hl[2][3][BB][HH];            // h bf16 lo
__device__ float g_Hfin[3][BB][HH];                      // final exact h
__device__ unsigned g_bar;
__device__ unsigned g_done;

__device__ __forceinline__ float* GXptr(int t) {
    return (t < 1024) ? (g_GXa + (size_t)t * CHUNK_PER_T)
                      : (g_GXb + (size_t)(t - 1024) * CHUNK_PER_T);
}

// ---------------- bf16 split helpers ----------------
__device__ __forceinline__ unsigned short f2b(float x) {
    return __bfloat16_as_ushort(__float2bfloat16(x));
}
__device__ __forceinline__ float b2f(unsigned short u) {
    return __bfloat162float(__ushort_as_bfloat16(u));
}
__device__ __forceinline__ void bsplit(float x, unsigned short& hi, unsigned short& lo) {
    hi = f2b(x);
    lo = f2b(x - b2f(hi));
}

// ---------------- mma / ldmatrix ----------------
__device__ __forceinline__ void mma16816(float* d, const uint32* a, uint32 b0, uint32 b1) {
    asm volatile(
        "mma.sync.aligned.m16n8k16.row.col.f32.bf16.bf16.f32 "
        "{%0,%1,%2,%3},{%4,%5,%6,%7},{%8,%9},{%0,%1,%2,%3};\n"
        : "+f"(d[0]), "+f"(d[1]), "+f"(d[2]), "+f"(d[3])
        : "r"(a[0]), "r"(a[1]), "r"(a[2]), "r"(a[3]), "r"(b0), "r"(b1));
}
__device__ __forceinline__ void ldsm4(uint32* r, const void* p) {
    uint32 a = (uint32)__cvta_generic_to_shared(p);
    asm volatile("ldmatrix.sync.aligned.m8n8.x4.shared.b16 {%0,%1,%2,%3},[%4];\n"
                 : "=r"(r[0]), "=r"(r[1]), "=r"(r[2]), "=r"(r[3]) : "r"(a));
}

// ======================================================================
// Split x -> bf16 hi/lo, layout [t][b][i]. grid 2048, 256 thr.
// ======================================================================
__global__ __launch_bounds__(256) void k_split_x(const float* __restrict__ x)
{
    const int t = blockIdx.x;
    #pragma unroll 4
    for (int p = 0; p < 32; ++p) {
        int idx = threadIdx.x + p * 256;         // 8192 float4 groups
        int b = idx >> 6, i4 = idx & 63;
        float4 v = __ldg((const float4*)(x + ((size_t)b * TT + t) * IN_D + i4 * 4));
        unsigned short h0, l0, h1, l1, h2, l2, h3, l3;
        bsplit(v.x, h0, l0); bsplit(v.y, h1, l1);
        bsplit(v.z, h2, l2); bsplit(v.w, h3, l3);
        uint2 hv = make_uint2((uint32)h0 | ((uint32)h1 << 16),
                              (uint32)h2 | ((uint32)h3 << 16));
        uint2 lv = make_uint2((uint32)l0 | ((uint32)l1 << 16),
                              (uint32)l2 | ((uint32)l3 << 16));
        size_t o = ((size_t)t * BB + b) * IN_D + i4 * 4;
        *(uint2*)(g_Xhi + o) = hv;
        *(uint2*)(g_Xlo + o) = lv;
    }
}

// Split + transpose Wx -> [n = kk*768 + o][k]. grid 2304, 256 thr.
__global__ __launch_bounds__(256) void k_split_wx(const float* __restrict__ Wx)
{
    const int n = blockIdx.x;
    const int kk = n / G3, o = n - kk * G3;
    const int k = threadIdx.x;
    float v = __ldg(Wx + ((size_t)kk * IN_D + k) * G3 + o);
    unsigned short hi, lo; bsplit(v, hi, lo);
    g_WxBhi[(size_t)n * IN_D + k] = hi;
    g_WxBlo[(size_t)n * IN_D + k] = lo;
}

// ======================================================================
// Kernel 1: GX[t][kk][b][o] = x_t @ Wx + bx  (bf16-split tensor mma)
// grid (36, 2048): blockIdx.x = kk*12 + otile(64). 256 thr = 8 warps
// laid out (wm = w&3 over 128 rows, wn = w>>2 over 64 cols).
// ======================================================================
#define KPB 72   /* smem pitch (bf16) for K=64 chunks; 144 B rows -> LDSM-clean */

__global__ __launch_bounds__(256) void k_xgemm(const float* __restrict__ bx)
{
    extern __shared__ unsigned short smx[];
    unsigned short* AHi = smx;                    // [128][KPB]
    unsigned short* ALo = smx + 128 * KPB;
    unsigned short* BHi = smx + 2 * 128 * KPB;    // [64][KPB]
    unsigned short* BLo = BHi + 64 * KPB;
    float* Ds = (float*)smx;                      // [128][68] reuse after mma

    const int t   = blockIdx.y;
    const int kk  = blockIdx.x / 12;
    const int o0  = (blockIdx.x % 12) * 64;
    const int tid = threadIdx.x;
    const int w = tid >> 5, lane = tid & 31;
    const int g = lane >> 2, tig = lane & 3;
    const int wm = w & 3, wn = w >> 2;
    const int lr = lane & 15, lc = (lane >> 4) * 8;          // A ldsm addr parts
    const int br = ((lane >> 4) & 1) * 8 + (lane & 7);       // B ldsm row part
    const int bc = ((lane >> 3) & 1) * 8;                    // B ldsm col part

    float acc[2][4][4];
    #pragma unroll
    for (int mt = 0; mt < 2; ++mt)
        #pragma unroll
        for (int nt = 0; nt < 4; ++nt)
            #pragma unroll
            for (int c = 0; c < 4; ++c) acc[mt][nt][c] = 0.f;

    for (int kc = 0; kc < 4; ++kc) {
        // stage A: 128 b x 64 k (hi & lo), uint4 = 8 bf16
        #pragma unroll
        for (int p = 0; p < 4; ++p) {
            int idx = tid + p * 256;
            int b = idx >> 3, k8 = idx & 7;
            size_t go = ((size_t)t * BB + b) * IN_D + kc * 64 + k8 * 8;
            *(uint4*)(AHi + b * KPB + k8 * 8) = __ldg((const uint4*)(g_Xhi + go));
            *(uint4*)(ALo + b * KPB + k8 * 8) = __ldg((const uint4*)(g_Xlo + go));
        }
        // stage B: 64 n x 64 k
        #pragma unroll
        for (int p = 0; p < 2; ++p) {
            int idx = tid + p * 256;
            int n = idx >> 3, k8 = idx & 7;
            size_t go = (size_t)(kk * G3 + o0 + n) * IN_D + kc * 64 + k8 * 8;
            *(uint4*)(BHi + n * KPB + k8 * 8) = __ldg((const uint4*)(g_WxBhi + go));
            *(uint4*)(BLo + n * KPB + k8 * 8) = __ldg((const uint4*)(g_WxBlo + go));
        }
        __syncthreads();

        #pragma unroll
        for (int kt = 0; kt < 4; ++kt) {
            int k0 = kt * 16;
            uint32 ah[2][4], al[2][4];
            #pragma unroll
            for (int mt = 0; mt < 2; ++mt) {
                int R = wm * 32 + mt * 16 + lr;
                ldsm4(ah[mt], AHi + R * KPB + k0 + lc);
                ldsm4(al[mt], ALo + R * KPB + k0 + lc);
            }
            uint32 bh[4][2], bl[4][2];
            #pragma unroll
            for (int p = 0; p < 2; ++p) {          // n-tile pair
                uint32 r4[4];
                int R = wn * 32 + p * 16 + br;
                ldsm4(r4, BHi + R * KPB + k0 + bc);
                bh[2*p][0] = r4[0]; bh[2*p][1] = r4[1];
                bh[2*p+1][0] = r4[2]; bh[2*p+1][1] = r4[3];
                ldsm4(r4, BLo + R * KPB + k0 + bc);
                bl[2*p][0] = r4[0]; bl[2*p][1] = r4[1];
                bl[2*p+1][0] = r4[2]; bl[2*p+1][1] = r4[3];
            }
            #pragma unroll
            for (int mt = 0; mt < 2; ++mt)
                #pragma unroll
                for (int nt = 0; nt < 4; ++nt) {
                    mma16816(acc[mt][nt], ah[mt], bh[nt][0], bh[nt][1]);
                    mma16816(acc[mt][nt], ah[mt], bl[nt][0], bl[nt][1]);
                    mma16816(acc[mt][nt], al[mt], bh[nt][0], bh[nt][1]);
                }
        }
        __syncthreads();
    }

    // dump C -> Ds[b][o_local], pitch 68
    #pragma unroll
    for (int mt = 0; mt < 2; ++mt)
        #pragma unroll
        for (int nt = 0; nt < 4; ++nt)
            #pragma unroll
            for (int c = 0; c < 4; ++c) {
                int row = wm * 32 + mt * 16 + g + (c >> 1) * 8;   // batch
                int col = wn * 32 + nt * 8 + 2 * tig + (c & 1);   // o local
                Ds[row * 68 + col] = acc[mt][nt][c];
            }
    __syncthreads();

    float* GX = GXptr(t);
    #pragma unroll
    for (int p = 0; p < 8; ++p) {
        int idx = tid + p * 256;                  // 2048 = 128 b x 16 o4
        int b = idx >> 4, o4 = idx & 15;
        float4 v = *(const float4*)(Ds + b * 68 + o4 * 4);
        float4 c = __ldg((const float4*)(bx + kk * G3 + o0 + o4 * 4));
        v.x += c.x; v.y += c.y; v.z += c.z; v.w += c.w;
        *(float4*)(GX + ((size_t)(kk * BB + b)) * G3 + o0 + o4 * 4) = v;
    }
}

// ======================================================================
// Grid barrier (96 co-resident blocks) — proven pattern from R12.
// ======================================================================
__device__ __forceinline__ void arrive_wait(unsigned target)
{
    __threadfence();
    __syncthreads();
    if (threadIdx.x == 0) {
        atomicAdd(&g_bar, 1u);
        unsigned v;
        do {
            asm volatile("ld.volatile.global.u32 %0, [%1];"
                         : "=r"(v) : "l"(&g_bar) : "memory");
        } while (v < target);
        __threadfence();
    }
    __syncthreads();
}

// ======================================================================
// Kernel 2: persistent recurrence, tensor-core gh.
// 96 blocks x 128 thr (1 block/SM via 149 KB smem). Block = (kk, J0, B0).
// Wh^T slice [96 n][256 k] bf16 hi/lo resident in smem. h exchanged as
// bf16 hi/lo via L2; exact fp32 h piece kept in smem (block's own outputs).
// Warps: wm = w&1 (16 rows of 32), wn = w>>1 (48 cols of 96).
// ======================================================================
#define WP 264   /* smem pitch (bf16) for K=256 tiles; 528 B rows -> LDSM-clean */

__global__ __launch_bounds__(128, 1) void k_recur(const float* __restrict__ h0,
                                                  const float* __restrict__ Wh,
                                                  const float* __restrict__ bh)
{
    extern __shared__ unsigned short sm[];
    unsigned short* WhHi = sm;                   // [96][WP]
    unsigned short* WhLo = sm + 96 * WP;
    unsigned short* AHi  = sm + 2 * 96 * WP;     // [32][WP]
    unsigned short* ALo  = AHi + 32 * WP;
    float* FS  = (float*)(sm + 2 * 96 * WP + 2 * 32 * WP);
    float* Cs  = FS;                             // [32][100]
    float* Hex = FS + 3200;                      // [32][33] exact fp32 h piece
    float* bhs = FS + 3200 + 1056;               // [96]

    const int tid = threadIdx.x;
    const int blk = blockIdx.x;
    const int kk  = blk / 32;
    const int rem = blk - kk * 32;
    const int J0  = (rem & 7) * 32;
    const int B0  = (rem >> 3) * 32;
    const int w = tid >> 5, lane = tid & 31;
    const int wm = w & 1, wn = w >> 1;
    const int lr = lane & 15, lc = (lane >> 4) * 8;
    const int br = ((lane >> 4) & 1) * 8 + (lane & 7);
    const int bc = ((lane >> 3) & 1) * 8;
    // combine mapping: thread owns (b = tid>>2, u = (tid&3)*8 .. +7)
    const int cb = tid >> 2, cu = (tid & 3) * 8;

    // ---- init: resident Wh^T slice, split to bf16 hi/lo ----
    for (int q = tid; q < 96 * 256; q += 128) {
        int n = q >> 8, i = q & 255;             // n = g*32 + j
        int gG = n >> 5, j = n & 31;
        float v = __ldg(Wh + ((size_t)kk * HH + i) * G3 + gG * HH + J0 + j);
        unsigned short hi, lo; bsplit(v, hi, lo);
        WhHi[n * WP + i] = hi;
        WhLo[n * WP + i] = lo;
    }
    if (tid < 96)
        bhs[tid] = __ldg(bh + kk * G3 + (tid >> 5) * HH + J0 + (tid & 31));

    // ---- init: h0 -> exact smem piece + global bf16 buffers ----
    {
        unsigned short hi8[8], lo8[8];
        #pragma unroll
        for (int e = 0; e < 8; ++e) {
            float v = __ldg(h0 + ((size_t)kk * BB + B0 + cb) * HH + J0 + cu + e);
            Hex[cb * 33 + cu + e] = v;
            bsplit(v, hi8[e], lo8[e]);
        }
        size_t o = ((size_t)kk * BB + B0 + cb) * HH + J0 + cu;
        *(uint4*)(&g_Hh[0][0][0][0] + o) = *(uint4*)hi8;
        *(uint4*)(&g_Hl[0][0][0][0] + o) = *(uint4*)lo8;
    }
    arrive_wait(NBLK * 1u);

    for (int s = 0; s < TT; ++s) {
        const int cur = s & 1, nxt = cur ^ 1;
        const float* GX = GXptr(s);

        // gx prefetch (independent of h): 3 gates x 8 units for (cb, cu)
        float gx[3][8];
        #pragma unroll
        for (int gG = 0; gG < 3; ++gG) {
            size_t o = ((size_t)(kk * BB + B0 + cb)) * G3 + gG * HH + J0 + cu;
            float4 v0 = __ldg((const float4*)(GX + o));
            float4 v1 = __ldg((const float4*)(GX + o + 4));
            gx[gG][0] = v0.x; gx[gG][1] = v0.y; gx[gG][2] = v0.z; gx[gG][3] = v0.w;
            gx[gG][4] = v1.x; gx[gG][5] = v1.y; gx[gG][6] = v1.z; gx[gG][7] = v1.w;
        }

        // stage A: h tile [32 b][256] hi/lo from L2
        const unsigned short* srcH = &g_Hh[cur][kk][0][0];
        const unsigned short* srcL = &g_Hl[cur][kk][0][0];
        #pragma unroll
        for (int p = 0; p < 8; ++p) {
            int idx = tid + p * 128;             // 1024 = 32 r x 32 c8
            int r = idx >> 5, c8 = idx & 31;
            size_t go = ((size_t)(B0 + r)) * HH + c8 * 8;
            *(uint4*)(AHi + r * WP + c8 * 8) = __ldcg((const uint4*)(srcH + go));
            *(uint4*)(ALo + r * WP + c8 * 8) = __ldcg((const uint4*)(srcL + go));
        }
        __syncthreads();

        // gh = h @ Wh^T : 16 k-iters, 6 n-tiles, 3 split passes
        float acc[6][4];
        #pragma unroll
        for (int nt = 0; nt < 6; ++nt)
            #pragma unroll
            for (int c = 0; c < 4; ++c) acc[nt][c] = 0.f;

        #pragma unroll 4
        for (int kt = 0; kt < 16; ++kt) {
            int k0 = kt * 16;
            uint32 ah[4], al[4];
            ldsm4(ah, AHi + (wm * 16 + lr) * WP + k0 + lc);
            ldsm4(al, ALo + (wm * 16 + lr) * WP + k0 + lc);
            uint32 bhf[6][2], blf[6][2];
            #pragma unroll
            for (int p = 0; p < 3; ++p) {
                uint32 r4[4];
                int R = wn * 48 + p * 16 + br;
                ldsm4(r4, WhHi + R * WP + k0 + bc);
                bhf[2*p][0] = r4[0]; bhf[2*p][1] = r4[1];
                bhf[2*p+1][0] = r4[2]; bhf[2*p+1][1] = r4[3];
                ldsm4(r4, WhLo + R * WP + k0 + bc);
                blf[2*p][0] = r4[0]; blf[2*p][1] = r4[1];
                blf[2*p+1][0] = r4[2]; blf[2*p+1][1] = r4[3];
            }
            #pragma unroll
            for (int nt = 0; nt < 6; ++nt) {
                mma16816(acc[nt], ah, bhf[nt][0], bhf[nt][1]);
                mma16816(acc[nt], ah, blf[nt][0], blf[nt][1]);
                mma16816(acc[nt], al, bhf[nt][0], bhf[nt][1]);
            }
        }

        // dump C -> Cs[b][n], pitch 100
        #pragma unroll
        for (int nt = 0; nt < 6; ++nt)
            #pragma unroll
            for (int c = 0; c < 4; ++c) {
                int row = wm * 16 + (lane >> 2) + (c >> 1) * 8;
                int col = wn * 48 + nt * 8 + 2 * (lane & 3) + (c & 1);
                Cs[row * 100 + col] = acc[nt][c];
            }
        __syncthreads();

        // combine: gates + state update for (cb, cu..cu+7)
        unsigned short hi8[8], lo8[8];
        #pragma unroll
        for (int e = 0; e < 8; ++e) {
            int u = cu + e;
            float rr = gx[0][e] + Cs[cb * 100 +       u] + bhs[u];
            float zz = gx[1][e] + Cs[cb * 100 +  32 + u] + bhs[32 + u];
            float nn = gx[2][e] + Cs[cb * 100 +  64 + u] + bhs[64 + u];
            float r = 1.f / (1.f + __expf(-rr));
            float z = 1.f / (1.f + __expf(-zz));
            float n = tanhf(nn + r * (Cs[cb * 100 + 64 + u] + bhs[64 + u]) * 0.f
                            + fmaf(r, 0.f, 0.f) + 0.f);   // placeholder removed below
            (void)n;
            // correct gate math (n uses r * nh where nh is the h-side part only):
            float nh = Cs[cb * 100 + 64 + u] + bhs[64 + u];
            n = tanhf(gx[2][e] + r * nh);
            float hold = Hex[cb * 33 + u];
            float hnew = (1.f - z) * n + z * hold;
            Hex[cb * 33 + u] = hnew;
            bsplit(hnew, hi8[e], lo8[e]);
            if (s == TT - 1)
                g_Hfin[kk][B0 + cb][J0 + u] = hnew;
        }
        {
            size_t o = ((size_t)kk * BB + B0 + cb) * HH + J0 + cu;
            __stcg((uint4*)(&g_Hh[nxt][0][0][0] + o), *(uint4*)hi8);
            __stcg((uint4*)(&g_Hl[nxt][0][0][0] + o), *(uint4*)lo8);
        }

        arrive_wait((unsigned)NBLK * (unsigned)(s + 2));
    }

    if (tid == 0) {
        unsigned old = atomicAdd(&g_done, 1u);
        if (old == NBLK - 1) { g_bar = 0u; g_done = 0u; __threadfence(); }
    }
}

// ======================================================================
// Epilogue: out = elu(sum_k h @ W_fc + b_fc); feature = mean_b h
// ======================================================================
__global__ void k_fc(const float* __restrict__ Wfc, const float* __restrict__ bfc,
                     float* __restrict__ out)
{
    __shared__ float pooled[256];
    const int b = blockIdx.x, o = threadIdx.x;
    pooled[o] = g_Hfin[0][b][o] + g_Hfin[1][b][o] + g_Hfin[2][b][o];
    __syncthreads();
    float s = __ldg(bfc + o);
    #pragma unroll 8
    for (int j = 0; j < 256; ++j)
        s = fmaf(pooled[j], __ldg(Wfc + j * 256 + o), s);
    out[b * 256 + o] = (s > 0.f) ? s : expm1f(s);
}

__global__ void k_feat(float* __restrict__ outF)
{
    const int k = blockIdx.x, u = threadIdx.x;
    float s = 0.f;
    #pragma unroll 4
    for (int b = 0; b < 128; ++b) s += g_Hfin[k][b][u];
    outF[k * 256 + u] = s * (1.f / 128.f);
}

// ======================================================================
extern "C" void kernel_launch(void* const* d_in, const int* in_sizes, int n_in,
                              void* d_out, int out_size)
{
    const float* x   = (const float*)d_in[0];   // [128, 2048, 256]
    const float* h0  = (const float*)d_in[1];   // [1, 3, 128, 256]
    const float* Wx  = (const float*)d_in[2];   // [3, 256, 768]
    const float* Wh  = (const float*)d_in[3];   // [3, 256, 768]
    const float* bx  = (const float*)d_in[4];   // [3, 768]
    const float* bh  = (const float*)d_in[5];   // [3, 768]
    const float* Wfc = (const float*)d_in[6];   // [256, 256]
    const float* bfc = (const float*)d_in[7];   // [256]
    float* out = (float*)d_out;                 // out[128*256] ++ feature[3*256]

    const int smem_x = 2 * (128 + 64) * KPB * (int)sizeof(unsigned short); // 55296
    const int smem_r = 2 * (96 + 32) * WP * (int)sizeof(unsigned short)
                     + (3200 + 1056 + 96) * (int)sizeof(float);            // 152576
    cudaFuncSetAttribute(k_xgemm, cudaFuncAttributeMaxDynamicSharedMemorySize, smem_x);
    cudaFuncSetAttribute(k_recur, cudaFuncAttributeMaxDynamicSharedMemorySize, smem_r);

    k_split_x<<<TT, 256>>>(x);
    k_split_wx<<<3 * G3, 256>>>(Wx);
    k_xgemm<<<dim3(36, TT), 256, smem_x>>>(bx);
    k_recur<<<NBLK, 128, smem_r>>>(h0, Wh, bh);
    k_fc<<<128, 256>>>(Wfc, bfc, out);
    k_feat<<<3, 256>>>(out + 128 * 256);
    (void)in_sizes; (void)n_in; (void)out_size;
}

// round 16
// speedup vs baseline: 1.7958x; 1.0458x over previous
#include <cuda_runtime.h>
#include <cuda_bf16.h>
#include <cstdint>

typedef unsigned int uint32;

#define TT    2048
#define BB    128
#define IN_D  256
#define HH    256
#define G3    768
#define NBLK  96
#define CHUNK_PER_T (3 * G3 * BB)      /* floats per timestep of GX */

// ---------------- static device scratch ----------------
__device__ float g_GXa[(size_t)1024 * CHUNK_PER_T];      // t in [0,1024)
__device__ float g_GXb[(size_t)1024 * CHUNK_PER_T];      // t in [1024,2048)
__device__ unsigned short g_Xhi[(size_t)TT * BB * IN_D]; // x split  [t][b][i]
__device__ unsigned short g_Xlo[(size_t)TT * BB * IN_D];
__device__ unsigned short g_WxBhi[3 * G3 * IN_D];        // Wx^T split [n][k]
__device__ unsigned short g_WxBlo[3 * G3 * IN_D];
__device__ unsigned short g_Hh[2][3][BB][HH];            // h bf16 hi, dbl-buffered
__device__ unsigned short g_Hl[2][3][BB][HH];            // h bf16 lo
__device__ float g_Hfin[3][BB][HH];                      // final exact h
__device__ unsigned g_gbar[12 * 32];                     // group barriers, 128B apart
__device__ unsigned g_done;

__device__ __forceinline__ float* GXptr(int t) {
    return (t < 1024) ? (g_GXa + (size_t)t * CHUNK_PER_T)
                      : (g_GXb + (size_t)(t - 1024) * CHUNK_PER_T);
}

// ---------------- bf16 split helpers ----------------
__device__ __forceinline__ unsigned short f2b(float x) {
    return __bfloat16_as_ushort(__float2bfloat16(x));
}
__device__ __forceinline__ float b2f(unsigned short u) {
    return __bfloat162float(__ushort_as_bfloat16(u));
}
__device__ __forceinline__ void bsplit(float x, unsigned short& hi, unsigned short& lo) {
    hi = f2b(x);
    lo = f2b(x - b2f(hi));
}

// ---------------- mma / ldmatrix ----------------
__device__ __forceinline__ void mma16816(float* d, const uint32* a, uint32 b0, uint32 b1) {
    asm volatile(
        "mma.sync.aligned.m16n8k16.row.col.f32.bf16.bf16.f32 "
        "{%0,%1,%2,%3},{%4,%5,%6,%7},{%8,%9},{%0,%1,%2,%3};\n"
        : "+f"(d[0]), "+f"(d[1]), "+f"(d[2]), "+f"(d[3])
        : "r"(a[0]), "r"(a[1]), "r"(a[2]), "r"(a[3]), "r"(b0), "r"(b1));
}
__device__ __forceinline__ void ldsm4(uint32* r, const void* p) {
    uint32 a = (uint32)__cvta_generic_to_shared(p);
    asm volatile("ldmatrix.sync.aligned.m8n8.x4.shared.b16 {%0,%1,%2,%3},[%4];\n"
                 : "=r"(r[0]), "=r"(r[1]), "=r"(r[2]), "=r"(r[3]) : "r"(a));
}

// ======================================================================
// Split x -> bf16 hi/lo, layout [t][b][i]. grid 2048, 256 thr.
// ======================================================================
__global__ __launch_bounds__(256) void k_split_x(const float* __restrict__ x)
{
    const int t = blockIdx.x;
    #pragma unroll 4
    for (int p = 0; p < 32; ++p) {
        int idx = threadIdx.x + p * 256;         // 8192 float4 groups
        int b = idx >> 6, i4 = idx & 63;
        float4 v = __ldg((const float4*)(x + ((size_t)b * TT + t) * IN_D + i4 * 4));
        unsigned short h0, l0, h1, l1, h2, l2, h3, l3;
        bsplit(v.x, h0, l0); bsplit(v.y, h1, l1);
        bsplit(v.z, h2, l2); bsplit(v.w, h3, l3);
        uint2 hv = make_uint2((uint32)h0 | ((uint32)h1 << 16),
                              (uint32)h2 | ((uint32)h3 << 16));
        uint2 lv = make_uint2((uint32)l0 | ((uint32)l1 << 16),
                              (uint32)l2 | ((uint32)l3 << 16));
        size_t o = ((size_t)t * BB + b) * IN_D + i4 * 4;
        *(uint2*)(g_Xhi + o) = hv;
        *(uint2*)(g_Xlo + o) = lv;
    }
}

// Split + transpose Wx -> [n = kk*768 + o][k]. grid 2304, 256 thr.
__global__ __launch_bounds__(256) void k_split_wx(const float* __restrict__ Wx)
{
    const int n = blockIdx.x;
    const int kk = n / G3, o = n - kk * G3;
    const int k = threadIdx.x;
    float v = __ldg(Wx + ((size_t)kk * IN_D + k) * G3 + o);
    unsigned short hi, lo; bsplit(v, hi, lo);
    g_WxBhi[(size_t)n * IN_D + k] = hi;
    g_WxBlo[(size_t)n * IN_D + k] = lo;
}

// ======================================================================
// Kernel 1: GX[t][kk][b][o] = x_t @ Wx + bx  (bf16-split tensor mma)
// grid (36, 2048): blockIdx.x = kk*12 + otile(64). 256 thr = 8 warps
// (wm = w&3 over 128 rows, wn = w>>2 over 64 cols). [unchanged, proven]
// ======================================================================
#define KPB 72   /* smem pitch (bf16) for K=64 chunks */

__global__ __launch_bounds__(256) void k_xgemm(const float* __restrict__ bx)
{
    extern __shared__ unsigned short smx[];
    unsigned short* AHi = smx;                    // [128][KPB]
    unsigned short* ALo = smx + 128 * KPB;
    unsigned short* BHi = smx + 2 * 128 * KPB;    // [64][KPB]
    unsigned short* BLo = BHi + 64 * KPB;
    float* Ds = (float*)smx;                      // [128][68] reuse after mma

    const int t   = blockIdx.y;
    const int kk  = blockIdx.x / 12;
    const int o0  = (blockIdx.x % 12) * 64;
    const int tid = threadIdx.x;
    const int w = tid >> 5, lane = tid & 31;
    const int g = lane >> 2, tig = lane & 3;
    const int wm = w & 3, wn = w >> 2;
    const int lr = lane & 15, lc = (lane >> 4) * 8;
    const int br = ((lane >> 4) & 1) * 8 + (lane & 7);
    const int bc = ((lane >> 3) & 1) * 8;

    float acc[2][4][4];
    #pragma unroll
    for (int mt = 0; mt < 2; ++mt)
        #pragma unroll
        for (int nt = 0; nt < 4; ++nt)
            #pragma unroll
            for (int c = 0; c < 4; ++c) acc[mt][nt][c] = 0.f;

    for (int kc = 0; kc < 4; ++kc) {
        #pragma unroll
        for (int p = 0; p < 4; ++p) {
            int idx = tid + p * 256;
            int b = idx >> 3, k8 = idx & 7;
            size_t go = ((size_t)t * BB + b) * IN_D + kc * 64 + k8 * 8;
            *(uint4*)(AHi + b * KPB + k8 * 8) = __ldg((const uint4*)(g_Xhi + go));
            *(uint4*)(ALo + b * KPB + k8 * 8) = __ldg((const uint4*)(g_Xlo + go));
        }
        #pragma unroll
        for (int p = 0; p < 2; ++p) {
            int idx = tid + p * 256;
            int n = idx >> 3, k8 = idx & 7;
            size_t go = (size_t)(kk * G3 + o0 + n) * IN_D + kc * 64 + k8 * 8;
            *(uint4*)(BHi + n * KPB + k8 * 8) = __ldg((const uint4*)(g_WxBhi + go));
            *(uint4*)(BLo + n * KPB + k8 * 8) = __ldg((const uint4*)(g_WxBlo + go));
        }
        __syncthreads();

        #pragma unroll
        for (int kt = 0; kt < 4; ++kt) {
            int k0 = kt * 16;
            uint32 ah[2][4], al[2][4];
            #pragma unroll
            for (int mt = 0; mt < 2; ++mt) {
                int R = wm * 32 + mt * 16 + lr;
                ldsm4(ah[mt], AHi + R * KPB + k0 + lc);
                ldsm4(al[mt], ALo + R * KPB + k0 + lc);
            }
            uint32 bh[4][2], bl[4][2];
            #pragma unroll
            for (int p = 0; p < 2; ++p) {
                uint32 r4[4];
                int R = wn * 32 + p * 16 + br;
                ldsm4(r4, BHi + R * KPB + k0 + bc);
                bh[2*p][0] = r4[0]; bh[2*p][1] = r4[1];
                bh[2*p+1][0] = r4[2]; bh[2*p+1][1] = r4[3];
                ldsm4(r4, BLo + R * KPB + k0 + bc);
                bl[2*p][0] = r4[0]; bl[2*p][1] = r4[1];
                bl[2*p+1][0] = r4[2]; bl[2*p+1][1] = r4[3];
            }
            #pragma unroll
            for (int mt = 0; mt < 2; ++mt)
                #pragma unroll
                for (int nt = 0; nt < 4; ++nt) {
                    mma16816(acc[mt][nt], ah[mt], bh[nt][0], bh[nt][1]);
                    mma16816(acc[mt][nt], ah[mt], bl[nt][0], bl[nt][1]);
                    mma16816(acc[mt][nt], al[mt], bh[nt][0], bh[nt][1]);
                }
        }
        __syncthreads();
    }

    #pragma unroll
    for (int mt = 0; mt < 2; ++mt)
        #pragma unroll
        for (int nt = 0; nt < 4; ++nt)
            #pragma unroll
            for (int c = 0; c < 4; ++c) {
                int row = wm * 32 + mt * 16 + g + (c >> 1) * 8;
                int col = wn * 32 + nt * 8 + 2 * tig + (c & 1);
                Ds[row * 68 + col] = acc[mt][nt][c];
            }
    __syncthreads();

    float* GX = GXptr(t);
    #pragma unroll
    for (int p = 0; p < 8; ++p) {
        int idx = tid + p * 256;
        int b = idx >> 4, o4 = idx & 15;
        float4 v = *(const float4*)(Ds + b * 68 + o4 * 4);
        float4 c = __ldg((const float4*)(bx + kk * G3 + o0 + o4 * 4));
        v.x += c.x; v.y += c.y; v.z += c.z; v.w += c.w;
        *(float4*)(GX + ((size_t)(kk * BB + b)) * G3 + o0 + o4 * 4) = v;
    }
}

// ======================================================================
// Group barrier: 8 co-resident blocks sharing (kk, B0).
// ======================================================================
__device__ __forceinline__ void group_barrier(unsigned* ctr, unsigned target)
{
    __threadfence();
    __syncthreads();
    if (threadIdx.x == 0) {
        atomicAdd(ctr, 1u);
        unsigned v;
        do {
            asm volatile("ld.volatile.global.u32 %0, [%1];"
                         : "=r"(v) : "l"(ctr) : "memory");
        } while (v < target);
        __threadfence();
    }
    __syncthreads();
}

// ======================================================================
// Kernel 2: persistent recurrence, tensor-core gh. 96 blocks x 256 thr.
// Block = (kk, J0 32-unit slice, B0 32-batch tile). Only the 8 blocks
// sharing (kk, B0) exchange h -> per-group barrier.
// Warps: wk = w>>1 (K quarter, 64), wn = w&1 (48-col half); each warp
// covers BOTH 16-row m-tiles (B fragments amortized 2x).
// Wh^T slice bf16 hi/lo resident in smem; h exchanged as bf16 hi/lo via
// L2 (__stcg/__ldcg); exact fp32 h piece lives in smem (own outputs).
// ======================================================================
#define WP 264   /* smem pitch (bf16) for K=256 tiles */

__global__ __launch_bounds__(256, 1) void k_recur(const float* __restrict__ h0,
                                                  const float* __restrict__ Wh,
                                                  const float* __restrict__ bh)
{
    extern __shared__ unsigned short sm[];
    unsigned short* WhHi = sm;                   // [96][WP]
    unsigned short* WhLo = sm + 96 * WP;
    unsigned short* AHi  = sm + 2 * 96 * WP;     // [32][WP]
    unsigned short* ALo  = AHi + 32 * WP;
    float* FS  = (float*)(AHi + 2 * 32 * WP);
    float* CsB = FS;                             // [4][32][100] split-K partials
    float* Hex = FS + 4 * 3200;                  // [32][33] exact fp32 h piece
    float* bhs = FS + 4 * 3200 + 1056;           // [96]

    const int tid = threadIdx.x;
    const int blk = blockIdx.x;
    const int kk  = blk / 32;
    const int rem = blk - kk * 32;
    const int J0  = (rem & 7) * 32;
    const int B0  = (rem >> 3) * 32;
    unsigned* gbar = &g_gbar[(kk * 4 + (rem >> 3)) * 32];

    const int w = tid >> 5, lane = tid & 31;
    const int wk = w >> 1;           // 0..3 : K quarter
    const int wn = w & 1;            // 0..1 : 48-col half
    const int lr = lane & 15, lc = (lane >> 4) * 8;
    const int br = ((lane >> 4) & 1) * 8 + (lane & 7);
    const int bc = ((lane >> 3) & 1) * 8;
    // combine mapping: thread owns (b = tid>>3, u = (tid&7)*4 .. +3)
    const int cb = tid >> 3, cu = (tid & 7) * 4;

    // ---- init: resident Wh^T slice, split to bf16 hi/lo ----
    for (int q = tid; q < 96 * 256; q += 256) {
        int n = q >> 8, i = q & 255;             // n = g*32 + j
        int gG = n >> 5, j = n & 31;
        float v = __ldg(Wh + ((size_t)kk * HH + i) * G3 + gG * HH + J0 + j);
        unsigned short hi, lo; bsplit(v, hi, lo);
        WhHi[n * WP + i] = hi;
        WhLo[n * WP + i] = lo;
    }
    if (tid < 96)
        bhs[tid] = __ldg(bh + kk * G3 + (tid >> 5) * HH + J0 + (tid & 31));

    // ---- init: h0 -> exact smem piece + global bf16 buffers ----
    {
        unsigned short hi4[4], lo4[4];
        #pragma unroll
        for (int e = 0; e < 4; ++e) {
            float v = __ldg(h0 + ((size_t)kk * BB + B0 + cb) * HH + J0 + cu + e);
            Hex[cb * 33 + cu + e] = v;
            bsplit(v, hi4[e], lo4[e]);
        }
        size_t o = ((size_t)kk * BB + B0 + cb) * HH + J0 + cu;
        __stcg((uint2*)(&g_Hh[0][0][0][0] + o), *(uint2*)hi4);
        __stcg((uint2*)(&g_Hl[0][0][0][0] + o), *(uint2*)lo4);
    }
    group_barrier(gbar, 8u);

    for (int s = 0; s < TT; ++s) {
        const int cur = s & 1, nxt = cur ^ 1;
        const float* GX = GXptr(s);

        // gx prefetch (independent of h): 3 gates x 4 units for (cb, cu)
        float gx[3][4];
        #pragma unroll
        for (int gG = 0; gG < 3; ++gG) {
            float4 v = __ldg((const float4*)(
                GX + ((size_t)(kk * BB + B0 + cb)) * G3 + gG * HH + J0 + cu));
            gx[gG][0] = v.x; gx[gG][1] = v.y; gx[gG][2] = v.z; gx[gG][3] = v.w;
        }

        // stage A: h tile [32 b][256] hi/lo from L2
        const unsigned short* srcH = &g_Hh[cur][kk][0][0];
        const unsigned short* srcL = &g_Hl[cur][kk][0][0];
        #pragma unroll
        for (int p = 0; p < 4; ++p) {
            int idx = tid + p * 256;             // 1024 = 32 r x 32 c8
            int r = idx >> 5, c8 = idx & 31;
            size_t go = ((size_t)(B0 + r)) * HH + c8 * 8;
            *(uint4*)(AHi + r * WP + c8 * 8) = __ldcg((const uint4*)(srcH + go));
            *(uint4*)(ALo + r * WP + c8 * 8) = __ldcg((const uint4*)(srcL + go));
        }
        __syncthreads();

        // gh partial: warp covers m 0..31, n half (48), K quarter (64)
        float acc[2][6][4];
        #pragma unroll
        for (int mt = 0; mt < 2; ++mt)
            #pragma unroll
            for (int nt = 0; nt < 6; ++nt)
                #pragma unroll
                for (int c = 0; c < 4; ++c) acc[mt][nt][c] = 0.f;

        #pragma unroll
        for (int kt = 0; kt < 4; ++kt) {
            int k0 = wk * 64 + kt * 16;
            uint32 ah[2][4], al[2][4];
            #pragma unroll
            for (int mt = 0; mt < 2; ++mt) {
                int R = mt * 16 + lr;
                ldsm4(ah[mt], AHi + R * WP + k0 + lc);
                ldsm4(al[mt], ALo + R * WP + k0 + lc);
            }
            uint32 bhf[6][2], blf[6][2];
            #pragma unroll
            for (int p = 0; p < 3; ++p) {
                uint32 r4[4];
                int R = wn * 48 + p * 16 + br;
                ldsm4(r4, WhHi + R * WP + k0 + bc);
                bhf[2*p][0] = r4[0]; bhf[2*p][1] = r4[1];
                bhf[2*p+1][0] = r4[2]; bhf[2*p+1][1] = r4[3];
                ldsm4(r4, WhLo + R * WP + k0 + bc);
                blf[2*p][0] = r4[0]; blf[2*p][1] = r4[1];
                blf[2*p+1][0] = r4[2]; blf[2*p+1][1] = r4[3];
            }
            #pragma unroll
            for (int mt = 0; mt < 2; ++mt)
                #pragma unroll
                for (int nt = 0; nt < 6; ++nt) {
                    mma16816(acc[mt][nt], ah[mt], bhf[nt][0], bhf[nt][1]);
                    mma16816(acc[mt][nt], ah[mt], blf[nt][0], blf[nt][1]);
                    mma16816(acc[mt][nt], al[mt], bhf[nt][0], bhf[nt][1]);
                }
        }

        // dump partials -> CsB[wk][b][n], pitch 100
        float* Cs = CsB + wk * 3200;
        #pragma unroll
        for (int mt = 0; mt < 2; ++mt)
            #pragma unroll
            for (int nt = 0; nt < 6; ++nt)
                #pragma unroll
                for (int c = 0; c < 4; ++c) {
                    int row = mt * 16 + (lane >> 2) + (c >> 1) * 8;
                    int col = wn * 48 + nt * 8 + 2 * (lane & 3) + (c & 1);
                    Cs[row * 100 + col] = acc[mt][nt][c];
                }
        __syncthreads();

        // combine: gates + state update for (cb, cu..cu+3)
        unsigned short hi4[4], lo4[4];
        #pragma unroll
        for (int e = 0; e < 4; ++e) {
            int u = cu + e;
            int base = cb * 100 + u;
            float Cr = CsB[base] + CsB[3200 + base] + CsB[6400 + base] + CsB[9600 + base];
            float Cz = CsB[base + 32] + CsB[3200 + base + 32]
                     + CsB[6400 + base + 32] + CsB[9600 + base + 32];
            float Cn = CsB[base + 64] + CsB[3200 + base + 64]
                     + CsB[6400 + base + 64] + CsB[9600 + base + 64];
            float r = 1.f / (1.f + __expf(-(gx[0][e] + Cr + bhs[u])));
            float z = 1.f / (1.f + __expf(-(gx[1][e] + Cz + bhs[32 + u])));
            float nh = Cn + bhs[64 + u];
            float n = tanhf(gx[2][e] + r * nh);
            float hold = Hex[cb * 33 + u];
            float hnew = (1.f - z) * n + z * hold;
            Hex[cb * 33 + u] = hnew;
            bsplit(hnew, hi4[e], lo4[e]);
            if (s == TT - 1)
                g_Hfin[kk][B0 + cb][J0 + u] = hnew;
        }
        {
            size_t o = ((size_t)kk * BB + B0 + cb) * HH + J0 + cu;
            __stcg((uint2*)(&g_Hh[nxt][0][0][0] + o), *(uint2*)hi4);
            __stcg((uint2*)(&g_Hl[nxt][0][0][0] + o), *(uint2*)lo4);
        }

        group_barrier(gbar, 8u * (unsigned)(s + 2));
    }

    // Reset barrier counters so every graph replay starts clean.
    if (tid == 0) {
        unsigned old = atomicAdd(&g_done, 1u);
        if (old == NBLK - 1) {
            #pragma unroll
            for (int i = 0; i < 12; ++i) g_gbar[i * 32] = 0u;
            g_done = 0u;
            __threadfence();
        }
    }
}

// ======================================================================
// Epilogue: out = elu(sum_k h @ W_fc + b_fc); feature = mean_b h
// ======================================================================
__global__ void k_fc(const float* __restrict__ Wfc, const float* __restrict__ bfc,
                     float* __restrict__ out)
{
    __shared__ float pooled[256];
    const int b = blockIdx.x, o = threadIdx.x;
    pooled[o] = g_Hfin[0][b][o] + g_Hfin[1][b][o] + g_Hfin[2][b][o];
    __syncthreads();
    float s = __ldg(bfc + o);
    #pragma unroll 8
    for (int j = 0; j < 256; ++j)
        s = fmaf(pooled[j], __ldg(Wfc + j * 256 + o), s);
    out[b * 256 + o] = (s > 0.f) ? s : expm1f(s);
}

__global__ void k_feat(float* __restrict__ outF)
{
    const int k = blockIdx.x, u = threadIdx.x;
    float s = 0.f;
    #pragma unroll 4
    for (int b = 0; b < 128; ++b) s += g_Hfin[k][b][u];
    outF[k * 256 + u] = s * (1.f / 128.f);
}

// ======================================================================
extern "C" void kernel_launch(void* const* d_in, const int* in_sizes, int n_in,
                              void* d_out, int out_size)
{
    const float* x   = (const float*)d_in[0];   // [128, 2048, 256]
    const float* h0  = (const float*)d_in[1];   // [1, 3, 128, 256]
    const float* Wx  = (const float*)d_in[2];   // [3, 256, 768]
    const float* Wh  = (const float*)d_in[3];   // [3, 256, 768]
    const float* bx  = (const float*)d_in[4];   // [3, 768]
    const float* bh  = (const float*)d_in[5];   // [3, 768]
    const float* Wfc = (const float*)d_in[6];   // [256, 256]
    const float* bfc = (const float*)d_in[7];   // [256]
    float* out = (float*)d_out;                 // out[128*256] ++ feature[3*256]

    const int smem_x = 2 * (128 + 64) * KPB * (int)sizeof(unsigned short); // 55296
    const int smem_r = 2 * (96 + 32) * WP * (int)sizeof(unsigned short)
                     + (4 * 3200 + 1056 + 96) * (int)sizeof(float);        // 190976
    cudaFuncSetAttribute(k_xgemm, cudaFuncAttributeMaxDynamicSharedMemorySize, smem_x);
    cudaFuncSetAttribute(k_recur, cudaFuncAttributeMaxDynamicSharedMemorySize, smem_r);

    k_split_x<<<TT, 256>>>(x);
    k_split_wx<<<3 * G3, 256>>>(Wx);
    k_xgemm<<<dim3(36, TT), 256, smem_x>>>(bx);
    k_recur<<<NBLK, 256, smem_r>>>(h0, Wh, bh);
    k_fc<<<128, 256>>>(Wfc, bfc, out);
    k_feat<<<3, 256>>>(out + 128 * 256);
    (void)in_sizes; (void)n_in; (void)out_size;
}